// round 9
// baseline (speedup 1.0000x reference)
#include <cuda_runtime.h>
#include <cstdint>

// Problem dims (fixed by the dataset)
#define B_  64
#define T_  256
#define D_  512
#define H_  1024
#define M_  (B_ * T_)   // 16384

// GEMM tiling
#define BM 128
#define BN 128
#define BK 16
#define KSPLIT 2
#define KHALF (D_ / KSPLIT)   // 256

// Scratch (allocation-free rule: __device__ globals)
__device__ float g_pre2[KSPLIT][(size_t)M_ * H_];  // 128 MB: K-split partials
__device__ float g_part[256];

// ---------------------------------------------------------------------------
// Kernel 1: g_pre2[z][m,n] = sum_{k in half z} A[m,k] * W[n,k]  (+bias on z=0)
// 128x128x16 double-buffered SGEMM, 256 threads, 8x8 per-thread tile with 4+4
// split fragments. Split-K over blockIdx.z (2048 blocks -> ~1% wave tail).
// Inner product uses packed fma.rn.f32x2 (FFMA2); accumulators paired over
// adjacent n, per-component RN, per-accumulator k-ascending chain.
// ---------------------------------------------------------------------------
__global__ __launch_bounds__(256, 2) void gemm_bias_kernel(
    const float* __restrict__ A,
    const float* __restrict__ W,
    const float* __restrict__ bias)
{
    __shared__ float sA[2][BK][BM];
    __shared__ float sB[2][BK][BN];

    const int tid = threadIdx.x;
    const int bm = blockIdx.y * BM;
    const int bn = blockIdx.x * BN;
    const int kz = blockIdx.z;                 // K-half
    const int kbase = kz * KHALF;

    // Global->smem: each thread loads 2 float4 of A and 2 of W per K-tile
    const int lrow = tid >> 1;                 // 0..127
    const int lcol = (tid & 1) * 8;            // 0 or 8
    const float* Ap = A + (size_t)(bm + lrow) * D_ + kbase + lcol;
    const float* Wp = W + (size_t)(bn + lrow) * D_ + kbase + lcol;

    // Prime buffer 0
    {
        float4 a0 = *(const float4*)Ap;
        float4 a1 = *(const float4*)(Ap + 4);
        float4 w0 = *(const float4*)Wp;
        float4 w1 = *(const float4*)(Wp + 4);
        sA[0][lcol + 0][lrow] = a0.x; sA[0][lcol + 1][lrow] = a0.y;
        sA[0][lcol + 2][lrow] = a0.z; sA[0][lcol + 3][lrow] = a0.w;
        sA[0][lcol + 4][lrow] = a1.x; sA[0][lcol + 5][lrow] = a1.y;
        sA[0][lcol + 6][lrow] = a1.z; sA[0][lcol + 7][lrow] = a1.w;
        sB[0][lcol + 0][lrow] = w0.x; sB[0][lcol + 1][lrow] = w0.y;
        sB[0][lcol + 2][lrow] = w0.z; sB[0][lcol + 3][lrow] = w0.w;
        sB[0][lcol + 4][lrow] = w1.x; sB[0][lcol + 5][lrow] = w1.y;
        sB[0][lcol + 6][lrow] = w1.z; sB[0][lcol + 7][lrow] = w1.w;
    }
    __syncthreads();

    const int tx = tid & 15;   // n-direction
    const int ty = tid >> 4;   // m-direction

    // acc2[i][jp]: i = m-row (0..7), jp = n-pair (0..3); lo = even n.
    unsigned long long acc2[8][4];
#pragma unroll
    for (int i = 0; i < 8; i++)
#pragma unroll
        for (int jp = 0; jp < 4; jp++) acc2[i][jp] = 0ull;

    int buf = 0;
    for (int k0 = BK; k0 <= KHALF; k0 += BK) {
        const bool more = (k0 < KHALF);
        float4 na0, na1, nw0, nw1;
        if (more) {
            na0 = *(const float4*)(Ap + k0);
            na1 = *(const float4*)(Ap + k0 + 4);
            nw0 = *(const float4*)(Wp + k0);
            nw1 = *(const float4*)(Wp + k0 + 4);
        }
#pragma unroll
        for (int kk = 0; kk < BK; kk++) {
            float ra[8];
            unsigned long long rb2[4];
            *(float4*)&ra[0] = *(const float4*)&sA[buf][kk][ty * 4];
            *(float4*)&ra[4] = *(const float4*)&sA[buf][kk][64 + ty * 4];
            *(ulonglong2*)&rb2[0] = *(const ulonglong2*)&sB[buf][kk][tx * 4];
            *(ulonglong2*)&rb2[2] = *(const ulonglong2*)&sB[buf][kk][64 + tx * 4];
#pragma unroll
            for (int i = 0; i < 8; i++) {
                unsigned long long a2;
                asm("mov.b64 %0, {%1, %1};" : "=l"(a2) : "f"(ra[i]));
#pragma unroll
                for (int jp = 0; jp < 4; jp++) {
                    asm("fma.rn.f32x2 %0, %1, %2, %0;"
                        : "+l"(acc2[i][jp])
                        : "l"(a2), "l"(rb2[jp]));
                }
            }
        }
        if (more) {
            buf ^= 1;
            sA[buf][lcol + 0][lrow] = na0.x; sA[buf][lcol + 1][lrow] = na0.y;
            sA[buf][lcol + 2][lrow] = na0.z; sA[buf][lcol + 3][lrow] = na0.w;
            sA[buf][lcol + 4][lrow] = na1.x; sA[buf][lcol + 5][lrow] = na1.y;
            sA[buf][lcol + 6][lrow] = na1.z; sA[buf][lcol + 7][lrow] = na1.w;
            sB[buf][lcol + 0][lrow] = nw0.x; sB[buf][lcol + 1][lrow] = nw0.y;
            sB[buf][lcol + 2][lrow] = nw0.z; sB[buf][lcol + 3][lrow] = nw0.w;
            sB[buf][lcol + 4][lrow] = nw1.x; sB[buf][lcol + 5][lrow] = nw1.y;
            sB[buf][lcol + 6][lrow] = nw1.z; sB[buf][lcol + 7][lrow] = nw1.w;
            __syncthreads();
        }
    }

    // Unpack accumulator pairs back to the scalar 8x8 view
    float acc[8][8];
#pragma unroll
    for (int i = 0; i < 8; i++)
#pragma unroll
        for (int jp = 0; jp < 4; jp++) {
            acc[i][2 * jp + 0] = __uint_as_float((uint32_t)(acc2[i][jp]));
            acc[i][2 * jp + 1] = __uint_as_float((uint32_t)(acc2[i][jp] >> 32));
        }

    // Epilogue: bias added only on the z=0 partial; store to this half's buffer
    float bs[8];
#pragma unroll
    for (int j = 0; j < 8; j++) {
        int n = bn + ((j < 4) ? (tx * 4 + j) : (64 + tx * 4 + (j - 4)));
        bs[j] = (kz == 0) ? bias[n] : 0.0f;
    }
    float* dst = g_pre2[kz];
#pragma unroll
    for (int i = 0; i < 8; i++) {
        int m = bm + ((i < 4) ? (ty * 4 + i) : (64 + ty * 4 + (i - 4)));
        float4 v0 = make_float4(acc[i][0] + bs[0], acc[i][1] + bs[1],
                                acc[i][2] + bs[2], acc[i][3] + bs[3]);
        float4 v1 = make_float4(acc[i][4] + bs[4], acc[i][5] + bs[5],
                                acc[i][6] + bs[6], acc[i][7] + bs[7]);
        *(float4*)&dst[(size_t)m * H_ + bn + tx * 4] = v0;
        *(float4*)&dst[(size_t)m * H_ + bn + 64 + tx * 4] = v1;
    }
}

// ---------------------------------------------------------------------------
// Kernel 2: ALIF recurrence over T per (b,h); combines the two K-partials.
// ---------------------------------------------------------------------------
__global__ __launch_bounds__(256) void alif_scan_kernel(
    const float* __restrict__ W_out)
{
    const int b  = blockIdx.x >> 2;
    const int hc = blockIdx.x & 3;
    const int h  = hc * 256 + threadIdx.x;

    const size_t off = (size_t)b * T_ * H_ + h;
    const float* p0 = g_pre2[0] + off;
    const float* p1 = g_pre2[1] + off;

    float mem = 0.0f, adapt = 0.0f, cnt = 0.0f;
#pragma unroll 8
    for (int t = 0; t < T_; t++) {
        float v = p0[(size_t)t * H_] + p1[(size_t)t * H_];
        mem = 0.9f * mem + v - adapt;
        float spk = (mem > 0.0f) ? 1.0f : 0.0f;
        adapt += 0.1f * spk;
        mem -= spk;
        cnt += spk;
    }

    float val = cnt * (1.0f / (float)T_) * W_out[h];

    __shared__ float red[256];
    red[threadIdx.x] = val;
    __syncthreads();
#pragma unroll
    for (int s = 128; s > 0; s >>= 1) {
        if (threadIdx.x < s) red[threadIdx.x] += red[threadIdx.x + s];
        __syncthreads();
    }
    if (threadIdx.x == 0) g_part[blockIdx.x] = red[0];
}

// ---------------------------------------------------------------------------
// Kernel 3: out[b] = sum_c g_part[b*4+c] + b_out[0]
// ---------------------------------------------------------------------------
__global__ void finalize_kernel(const float* __restrict__ b_out,
                                float* __restrict__ out)
{
    int b = threadIdx.x;
    if (b < B_) {
        float s = g_part[b * 4 + 0] + g_part[b * 4 + 1] +
                  g_part[b * 4 + 2] + g_part[b * 4 + 3];
        out[b] = s + b_out[0];
    }
}

extern "C" void kernel_launch(void* const* d_in, const int* in_sizes, int n_in,
                              void* d_out, int out_size)
{
    (void)in_sizes; (void)n_in; (void)out_size;
    const float* x     = (const float*)d_in[0];  // [64,256,512]
    const float* W_in  = (const float*)d_in[1];  // [1024,512]
    const float* b_in  = (const float*)d_in[2];  // [1024]
    const float* W_out = (const float*)d_in[3];  // [1,1024]
    const float* b_out = (const float*)d_in[4];  // [1]
    float* out = (float*)d_out;                  // [64,1]

    dim3 ggrid(H_ / BN, M_ / BM, KSPLIT);        // (8, 128, 2)
    gemm_bias_kernel<<<ggrid, 256>>>(x, W_in, b_in);
    alif_scan_kernel<<<256, 256>>>(W_out);
    finalize_kernel<<<1, 64>>>(b_out, out);
}